// round 3
// baseline (speedup 1.0000x reference)
#include <cuda_runtime.h>
#include <cuda_bf16.h>

// Problem constants (reference: N=100000, E=1000000, D=64)
#define MAXN 100000
#define DIMF 64

// Scratch (device globals; no allocation allowed)
__device__ float g_agg[MAXN * DIMF];
__device__ float g_h1[MAXN * DIMF];
__device__ float g_h2[MAXN * DIMF];

// ---------------------------------------------------------------------------
// Copy kernel: agg = x  (GIN identity term folded into the aggregate init)
// ---------------------------------------------------------------------------
__global__ void copy_kernel(const float4* __restrict__ src,
                            float4* __restrict__ dst, int n4) {
    int i = blockIdx.x * blockDim.x + threadIdx.x;
    if (i < n4) dst[i] = src[i];
}

// ---------------------------------------------------------------------------
// Scatter: agg[dst] += x[src] * ew   (16 threads per edge, vector red.v4.f32)
// ---------------------------------------------------------------------------
__global__ void scatter_kernel(const float4* __restrict__ x4,
                               const int* __restrict__ src,
                               const int* __restrict__ dst,
                               const float* __restrict__ ew,
                               float* __restrict__ agg,
                               int E) {
    int idx = blockIdx.x * blockDim.x + threadIdx.x;
    int e = idx >> 4;
    if (e >= E) return;
    int c = idx & 15;
    int s = __ldg(src + e);
    int d = __ldg(dst + e);
    float w = __ldg(ew + e);
    float4 v = x4[(size_t)s * 16 + c];
    float rx = v.x * w, ry = v.y * w, rz = v.z * w, rw = v.w * w;
    float* p = agg + ((size_t)d * 64 + c * 4);
    asm volatile("red.global.add.v4.f32 [%0], {%1,%2,%3,%4};"
                 :: "l"(p), "f"(rx), "f"(ry), "f"(rz), "f"(rw) : "memory");
}

// ---------------------------------------------------------------------------
// Fused MLP: out = [relu]( relu(agg @ W1 + b1) @ W2 + b2 )
//
// 128 rows per block, 256 threads. Register tiling 8 rows x 4 cols per thread.
// Lane mapping: rg = tid&15 (rows rg+16j), cg = tid>>4 (col group) -> the 16
// lanes of a half-warp share cg, so weight LDS are broadcast and input LDS are
// 16 contiguous float4 (conflict-free). Input staged transposed as
// in_v[k4][r] (float4 granularity, row stride 129 to de-conflict the
// transposing store); hid staged k-major as hid_v[h4][r] so GEMM2 reads the
// identical pattern. FMA-bound by ~3x over smem crossbar.
// ---------------------------------------------------------------------------
template<int H, bool RELU_OUT>
__global__ void __launch_bounds__(256, 2) mlp_kernel(
        const float4* __restrict__ agg4,
        const float* __restrict__ w1, const float* __restrict__ b1,
        const float* __restrict__ w2, const float* __restrict__ b2,
        float4* __restrict__ out4, int N) {
    constexpr int TR  = 128;      // rows per block
    constexpr int INS = 129;      // in_v row stride in float4 (transpose pad)
    constexpr int W1S = 68;       // w1t row stride (floats)
    constexpr int W2S = H + 4;    // w2t row stride (floats)

    extern __shared__ float sm[];
    float4* in_v  = (float4*)sm;                            // 16 * INS
    float*  w1t   = sm + 16 * INS * 4;                      // H * W1S  (w1t[c][k] = w1[k*H+c])
    float4* hid_v = (float4*)(w1t + H * W1S);               // (H/4) * TR
    float*  w2t   = (float*)(hid_v + (H / 4) * TR);         // 64 * W2S (w2t[c][h] = w2[h*64+c])
    float*  b1s   = w2t + 64 * W2S;                         // H
    float*  b2s   = b1s + H;                                // 64

    int tid  = threadIdx.x;
    int row0 = blockIdx.x * TR;
    int nrows = N - row0; if (nrows > TR) nrows = TR;

    // Load weights (transposed) + biases
    for (int i = tid; i < 64 * H; i += 256) {
        int k = i / H, c = i % H;
        w1t[c * W1S + k] = w1[i];
    }
    for (int i = tid; i < H * 64; i += 256) {
        int h = i / 64, c = i % 64;
        w2t[c * W2S + h] = w2[i];
    }
    if (tid < H)  b1s[tid] = b1[tid];
    if (tid < 64) b2s[tid] = b2[tid];

    // Stage input tile transposed at float4 granularity: in_v[k4][r]
    for (int i = tid; i < TR * 16; i += 256) {
        int r = i >> 4, k4 = i & 15;
        float4 v = make_float4(0.f, 0.f, 0.f, 0.f);
        if (r < nrows) v = agg4[(size_t)(row0 + r) * 16 + k4];
        in_v[k4 * INS + r] = v;
    }
    __syncthreads();

    const int rg = tid & 15;   // rows rg + 16j, j = 0..7
    const int cg = tid >> 4;   // column group (shared by 16 lanes -> broadcast)

    // GEMM1: hid = relu(in @ W1 + b1)
    #pragma unroll
    for (int p = 0; p < H / 64; ++p) {
        int c0 = (p * 16 + cg) * 4;
        float acc[8][4];
        #pragma unroll
        for (int j = 0; j < 8; j++) {
            acc[j][0] = b1s[c0];     acc[j][1] = b1s[c0 + 1];
            acc[j][2] = b1s[c0 + 2]; acc[j][3] = b1s[c0 + 3];
        }
        #pragma unroll
        for (int k4 = 0; k4 < 16; ++k4) {
            float4 wv0 = *(const float4*)(w1t + (c0 + 0) * W1S + k4 * 4);
            float4 wv1 = *(const float4*)(w1t + (c0 + 1) * W1S + k4 * 4);
            float4 wv2 = *(const float4*)(w1t + (c0 + 2) * W1S + k4 * 4);
            float4 wv3 = *(const float4*)(w1t + (c0 + 3) * W1S + k4 * 4);
            #pragma unroll
            for (int j = 0; j < 8; j++) {
                float4 iv = in_v[k4 * INS + rg + 16 * j];
                acc[j][0] += iv.x * wv0.x + iv.y * wv0.y + iv.z * wv0.z + iv.w * wv0.w;
                acc[j][1] += iv.x * wv1.x + iv.y * wv1.y + iv.z * wv1.z + iv.w * wv1.w;
                acc[j][2] += iv.x * wv2.x + iv.y * wv2.y + iv.z * wv2.z + iv.w * wv2.w;
                acc[j][3] += iv.x * wv3.x + iv.y * wv3.y + iv.z * wv3.z + iv.w * wv3.w;
            }
        }
        #pragma unroll
        for (int j = 0; j < 8; j++) {
            int r = rg + 16 * j;
            hid_v[(p * 16 + cg) * TR + r] = make_float4(
                fmaxf(acc[j][0], 0.f), fmaxf(acc[j][1], 0.f),
                fmaxf(acc[j][2], 0.f), fmaxf(acc[j][3], 0.f));
        }
    }
    __syncthreads();

    // GEMM2: out = hid @ W2 + b2  (+ optional relu)
    {
        int c0 = cg * 4;
        float acc[8][4];
        #pragma unroll
        for (int j = 0; j < 8; j++) {
            acc[j][0] = b2s[c0];     acc[j][1] = b2s[c0 + 1];
            acc[j][2] = b2s[c0 + 2]; acc[j][3] = b2s[c0 + 3];
        }
        #pragma unroll
        for (int h4 = 0; h4 < H / 4; ++h4) {
            float4 wv0 = *(const float4*)(w2t + (c0 + 0) * W2S + h4 * 4);
            float4 wv1 = *(const float4*)(w2t + (c0 + 1) * W2S + h4 * 4);
            float4 wv2 = *(const float4*)(w2t + (c0 + 2) * W2S + h4 * 4);
            float4 wv3 = *(const float4*)(w2t + (c0 + 3) * W2S + h4 * 4);
            #pragma unroll
            for (int j = 0; j < 8; j++) {
                float4 iv = hid_v[h4 * TR + rg + 16 * j];
                acc[j][0] += iv.x * wv0.x + iv.y * wv0.y + iv.z * wv0.z + iv.w * wv0.w;
                acc[j][1] += iv.x * wv1.x + iv.y * wv1.y + iv.z * wv1.z + iv.w * wv1.w;
                acc[j][2] += iv.x * wv2.x + iv.y * wv2.y + iv.z * wv2.z + iv.w * wv2.w;
                acc[j][3] += iv.x * wv3.x + iv.y * wv3.y + iv.z * wv3.z + iv.w * wv3.w;
            }
        }
        #pragma unroll
        for (int j = 0; j < 8; j++) {
            int r = rg + 16 * j;
            if (r < nrows) {
                float4 v;
                if (RELU_OUT) {
                    v = make_float4(fmaxf(acc[j][0], 0.f), fmaxf(acc[j][1], 0.f),
                                    fmaxf(acc[j][2], 0.f), fmaxf(acc[j][3], 0.f));
                } else {
                    v = make_float4(acc[j][0], acc[j][1], acc[j][2], acc[j][3]);
                }
                out4[(size_t)(row0 + r) * 16 + cg] = v;
            }
        }
    }
}

// ---------------------------------------------------------------------------
// Launch
// ---------------------------------------------------------------------------
static inline size_t mlp_smem(int H) {
    return (size_t)(16 * 129 * 4       // in_v (float4 -> floats)
                  + H * 68             // w1t
                  + (H / 4) * 128 * 4  // hid_v
                  + 64 * (H + 4)       // w2t
                  + H + 64) * sizeof(float);
}

extern "C" void kernel_launch(void* const* d_in, const int* in_sizes, int n_in,
                              void* d_out, int out_size) {
    const float* x   = (const float*)d_in[0];
    const int*   ei  = (const int*)d_in[1];
    const float* ew  = (const float*)d_in[2];
    const float* w11 = (const float*)d_in[3];
    const float* b11 = (const float*)d_in[4];
    const float* w12 = (const float*)d_in[5];
    const float* b12 = (const float*)d_in[6];
    const float* w21 = (const float*)d_in[7];
    const float* b21 = (const float*)d_in[8];
    const float* w22 = (const float*)d_in[9];
    const float* b22 = (const float*)d_in[10];
    const float* w31 = (const float*)d_in[11];
    const float* b31 = (const float*)d_in[12];
    const float* w32 = (const float*)d_in[13];
    const float* b32 = (const float*)d_in[14];
    float* out = (float*)d_out;

    int N = in_sizes[0] / DIMF;
    int E = in_sizes[1] / 2;
    const int* src = ei;
    const int* dst = ei + E;

    float *agg, *h1, *h2;
    cudaGetSymbolAddress((void**)&agg, g_agg);
    cudaGetSymbolAddress((void**)&h1, g_h1);
    cudaGetSymbolAddress((void**)&h2, g_h2);

    size_t sm64  = mlp_smem(64);
    size_t sm128 = mlp_smem(128);
    cudaFuncSetAttribute(mlp_kernel<64, true>,  cudaFuncAttributeMaxDynamicSharedMemorySize, (int)sm64);
    cudaFuncSetAttribute(mlp_kernel<128, true>, cudaFuncAttributeMaxDynamicSharedMemorySize, (int)sm128);
    cudaFuncSetAttribute(mlp_kernel<64, false>, cudaFuncAttributeMaxDynamicSharedMemorySize, (int)sm64);

    int n4 = N * 16;                         // float4 count of node features
    int cb = (n4 + 255) / 256;
    int sb = (E * 16 + 255) / 256;
    int mb = (N + 127) / 128;

    // Layer 1: 64 -> 64 -> 64, relu
    copy_kernel<<<cb, 256>>>((const float4*)x, (float4*)agg, n4);
    scatter_kernel<<<sb, 256>>>((const float4*)x, src, dst, ew, agg, E);
    mlp_kernel<64, true><<<mb, 256, sm64>>>((const float4*)agg, w11, b11, w12, b12, (float4*)h1, N);

    // Layer 2: 64 -> 128 -> 64, relu
    copy_kernel<<<cb, 256>>>((const float4*)h1, (float4*)agg, n4);
    scatter_kernel<<<sb, 256>>>((const float4*)h1, src, dst, ew, agg, E);
    mlp_kernel<128, true><<<mb, 256, sm128>>>((const float4*)agg, w21, b21, w22, b22, (float4*)h2, N);

    // Layer 3: 64 -> 64 -> 64, no relu
    copy_kernel<<<cb, 256>>>((const float4*)h2, (float4*)agg, n4);
    scatter_kernel<<<sb, 256>>>((const float4*)h2, src, dst, ew, agg, E);
    mlp_kernel<64, false><<<mb, 256, sm64>>>((const float4*)agg, w31, b31, w32, b32, (float4*)out, N);
}

// round 4
// speedup vs baseline: 1.6311x; 1.6311x over previous
#include <cuda_runtime.h>
#include <cuda_bf16.h>

// Problem constants (reference: N=100000, E=1000000, D=64)
#define MAXN 100000
#define DIMF 64

// Scratch (device globals; no allocation allowed)
__device__ float g_agg[MAXN * DIMF];
__device__ float g_h1[MAXN * DIMF];
__device__ float g_h2[MAXN * DIMF];

// ---------------------------------------------------------------------------
// Copy kernel: agg = x  (GIN identity term folded into the aggregate init)
// ---------------------------------------------------------------------------
__global__ void copy_kernel(const float4* __restrict__ src,
                            float4* __restrict__ dst, int n4) {
    int i = blockIdx.x * blockDim.x + threadIdx.x;
    if (i < n4) dst[i] = src[i];
}

// ---------------------------------------------------------------------------
// Scatter: agg[dst] += x[src] * ew   (16 threads per edge, vector red.v4.f32)
// ---------------------------------------------------------------------------
__global__ void scatter_kernel(const float4* __restrict__ x4,
                               const int* __restrict__ src,
                               const int* __restrict__ dst,
                               const float* __restrict__ ew,
                               float* __restrict__ agg,
                               int E) {
    int idx = blockIdx.x * blockDim.x + threadIdx.x;
    int e = idx >> 4;
    if (e >= E) return;
    int c = idx & 15;
    int s = __ldg(src + e);
    int d = __ldg(dst + e);
    float w = __ldg(ew + e);
    float4 v = x4[(size_t)s * 16 + c];
    float rx = v.x * w, ry = v.y * w, rz = v.z * w, rw = v.w * w;
    float* p = agg + ((size_t)d * 64 + c * 4);
    asm volatile("red.global.add.v4.f32 [%0], {%1,%2,%3,%4};"
                 :: "l"(p), "f"(rx), "f"(ry), "f"(rz), "f"(rw) : "memory");
}

// ---------------------------------------------------------------------------
// Fused MLP: out = [relu]( relu(agg @ W1 + b1) @ W2 + b2 )
//
// 64 rows/block, 256 threads, 4 rows x 4 cols register tile per thread.
// Lane mapping: rg = tid&15 (rows rg+16j), cg = tid>>4 (col group). The 16
// lanes of a half-warp share cg -> weight LDS are broadcast (bank-agnostic),
// input LDS are 16 consecutive float4 (conflict-free). GEMM1 results are held
// in registers across a sync so the in_v/w1t smem region can be reused for
// hid -> smem = 50KB (H=64) / 83KB (H=128) -> 3-4 / 2 blocks per SM.
// ---------------------------------------------------------------------------
template<int H, bool RELU_OUT>
__global__ void __launch_bounds__(256, 2) mlp_kernel(
        const float4* __restrict__ agg4,
        const float* __restrict__ w1, const float* __restrict__ b1,
        const float* __restrict__ w2, const float* __restrict__ b2,
        float4* __restrict__ out4, int N) {
    constexpr int TR  = 64;       // rows per block
    constexpr int INS = 65;       // in_v row stride in float4 (staging pad)
    constexpr int NP  = H / 64;   // col passes in GEMM1

    extern __shared__ float sm[];
    float4* in_v = (float4*)sm;               // 16 * INS float4   (in_v[k4][r])
    float*  w1t  = sm + 16 * INS * 4;         // H * 64            (w1t[c][k] = w1[k*H+c])
    float4* hid4 = (float4*)sm;               // (H/4) * 64 float4 (reuses in_v+w1t region)
    float*  w2t  = w1t + H * 64;              // 64 * H            (w2t[c][h] = w2[h*64+c])
    float*  b1s  = w2t + 64 * H;              // H
    float*  b2s  = b1s + H;                   // 64

    int tid  = threadIdx.x;
    int row0 = blockIdx.x * TR;
    int nrows = N - row0; if (nrows > TR) nrows = TR;

    // Phase 1: load weights (transposed) + biases, stage input transposed
    for (int i = tid; i < 64 * H; i += 256) {
        int k = i / H, c = i % H;
        w1t[c * 64 + k] = w1[i];
    }
    for (int i = tid; i < H * 64; i += 256) {
        int h = i / 64, c = i % 64;
        w2t[c * H + h] = w2[i];
    }
    if (tid < H)  b1s[tid] = b1[tid];
    if (tid < 64) b2s[tid] = b2[tid];

    for (int i = tid; i < TR * 16; i += 256) {
        int r = i >> 4, k4 = i & 15;
        float4 v = make_float4(0.f, 0.f, 0.f, 0.f);
        if (r < nrows) v = agg4[(size_t)(row0 + r) * 16 + k4];
        in_v[k4 * INS + r] = v;
    }
    __syncthreads();

    const int rg = tid & 15;   // rows rg + 16j, j = 0..3
    const int cg = tid >> 4;   // col group 0..15 (uniform per half-warp)

    // Phase 2: GEMM1, results kept in registers
    float acc1[NP][4][4];
    #pragma unroll
    for (int p = 0; p < NP; p++) {
        int c0 = (p * 16 + cg) * 4;
        #pragma unroll
        for (int j = 0; j < 4; j++) {
            acc1[p][j][0] = b1s[c0];     acc1[p][j][1] = b1s[c0 + 1];
            acc1[p][j][2] = b1s[c0 + 2]; acc1[p][j][3] = b1s[c0 + 3];
        }
    }
    #pragma unroll
    for (int k4 = 0; k4 < 16; ++k4) {
        float4 iv[4];
        #pragma unroll
        for (int j = 0; j < 4; j++) iv[j] = in_v[k4 * INS + rg + 16 * j];
        #pragma unroll
        for (int p = 0; p < NP; p++) {
            int c0 = (p * 16 + cg) * 4;
            float4 wv0 = *(const float4*)(w1t + (c0 + 0) * 64 + k4 * 4);
            float4 wv1 = *(const float4*)(w1t + (c0 + 1) * 64 + k4 * 4);
            float4 wv2 = *(const float4*)(w1t + (c0 + 2) * 64 + k4 * 4);
            float4 wv3 = *(const float4*)(w1t + (c0 + 3) * 64 + k4 * 4);
            #pragma unroll
            for (int j = 0; j < 4; j++) {
                acc1[p][j][0] += iv[j].x * wv0.x + iv[j].y * wv0.y + iv[j].z * wv0.z + iv[j].w * wv0.w;
                acc1[p][j][1] += iv[j].x * wv1.x + iv[j].y * wv1.y + iv[j].z * wv1.z + iv[j].w * wv1.w;
                acc1[p][j][2] += iv[j].x * wv2.x + iv[j].y * wv2.y + iv[j].z * wv2.z + iv[j].w * wv2.w;
                acc1[p][j][3] += iv[j].x * wv3.x + iv[j].y * wv3.y + iv[j].z * wv3.z + iv[j].w * wv3.w;
            }
        }
    }
    __syncthreads();   // all reads of in_v / w1t complete

    // Phase 3: store relu(hid) into the reused region, k-major: hid4[h4][r]
    #pragma unroll
    for (int p = 0; p < NP; p++) {
        #pragma unroll
        for (int j = 0; j < 4; j++) {
            hid4[(p * 16 + cg) * 64 + rg + 16 * j] = make_float4(
                fmaxf(acc1[p][j][0], 0.f), fmaxf(acc1[p][j][1], 0.f),
                fmaxf(acc1[p][j][2], 0.f), fmaxf(acc1[p][j][3], 0.f));
        }
    }
    __syncthreads();

    // Phase 4: GEMM2: out = hid @ W2 + b2  (+ optional relu)
    {
        int c0 = cg * 4;
        float acc[4][4];
        #pragma unroll
        for (int j = 0; j < 4; j++) {
            acc[j][0] = b2s[c0];     acc[j][1] = b2s[c0 + 1];
            acc[j][2] = b2s[c0 + 2]; acc[j][3] = b2s[c0 + 3];
        }
        #pragma unroll
        for (int h4 = 0; h4 < H / 4; ++h4) {
            float4 hv[4];
            #pragma unroll
            for (int j = 0; j < 4; j++) hv[j] = hid4[h4 * 64 + rg + 16 * j];
            float4 wv0 = *(const float4*)(w2t + (c0 + 0) * H + h4 * 4);
            float4 wv1 = *(const float4*)(w2t + (c0 + 1) * H + h4 * 4);
            float4 wv2 = *(const float4*)(w2t + (c0 + 2) * H + h4 * 4);
            float4 wv3 = *(const float4*)(w2t + (c0 + 3) * H + h4 * 4);
            #pragma unroll
            for (int j = 0; j < 4; j++) {
                acc[j][0] += hv[j].x * wv0.x + hv[j].y * wv0.y + hv[j].z * wv0.z + hv[j].w * wv0.w;
                acc[j][1] += hv[j].x * wv1.x + hv[j].y * wv1.y + hv[j].z * wv1.z + hv[j].w * wv1.w;
                acc[j][2] += hv[j].x * wv2.x + hv[j].y * wv2.y + hv[j].z * wv2.z + hv[j].w * wv2.w;
                acc[j][3] += hv[j].x * wv3.x + hv[j].y * wv3.y + hv[j].z * wv3.z + hv[j].w * wv3.w;
            }
        }
        #pragma unroll
        for (int j = 0; j < 4; j++) {
            int r = rg + 16 * j;
            if (r < nrows) {
                float4 v;
                if (RELU_OUT) {
                    v = make_float4(fmaxf(acc[j][0], 0.f), fmaxf(acc[j][1], 0.f),
                                    fmaxf(acc[j][2], 0.f), fmaxf(acc[j][3], 0.f));
                } else {
                    v = make_float4(acc[j][0], acc[j][1], acc[j][2], acc[j][3]);
                }
                out4[(size_t)(row0 + r) * 16 + cg] = v;
            }
        }
    }
}

// ---------------------------------------------------------------------------
// Launch
// ---------------------------------------------------------------------------
static inline size_t mlp_smem(int H) {
    size_t region0 = 16 * 65 * 4 + (size_t)H * 64;  // in_v + w1t (>= hid)
    return (region0 + 64 * H + H + 64) * sizeof(float);
}

extern "C" void kernel_launch(void* const* d_in, const int* in_sizes, int n_in,
                              void* d_out, int out_size) {
    const float* x   = (const float*)d_in[0];
    const int*   ei  = (const int*)d_in[1];
    const float* ew  = (const float*)d_in[2];
    const float* w11 = (const float*)d_in[3];
    const float* b11 = (const float*)d_in[4];
    const float* w12 = (const float*)d_in[5];
    const float* b12 = (const float*)d_in[6];
    const float* w21 = (const float*)d_in[7];
    const float* b21 = (const float*)d_in[8];
    const float* w22 = (const float*)d_in[9];
    const float* b22 = (const float*)d_in[10];
    const float* w31 = (const float*)d_in[11];
    const float* b31 = (const float*)d_in[12];
    const float* w32 = (const float*)d_in[13];
    const float* b32 = (const float*)d_in[14];
    float* out = (float*)d_out;

    int N = in_sizes[0] / DIMF;
    int E = in_sizes[1] / 2;
    const int* src = ei;
    const int* dst = ei + E;

    float *agg, *h1, *h2;
    cudaGetSymbolAddress((void**)&agg, g_agg);
    cudaGetSymbolAddress((void**)&h1, g_h1);
    cudaGetSymbolAddress((void**)&h2, g_h2);

    size_t sm64  = mlp_smem(64);
    size_t sm128 = mlp_smem(128);
    cudaFuncSetAttribute(mlp_kernel<64, true>,  cudaFuncAttributeMaxDynamicSharedMemorySize, (int)sm64);
    cudaFuncSetAttribute(mlp_kernel<128, true>, cudaFuncAttributeMaxDynamicSharedMemorySize, (int)sm128);
    cudaFuncSetAttribute(mlp_kernel<64, false>, cudaFuncAttributeMaxDynamicSharedMemorySize, (int)sm64);

    int n4 = N * 16;                         // float4 count of node features
    int cb = (n4 + 255) / 256;
    int sb = (E * 16 + 255) / 256;
    int mb = (N + 63) / 64;

    // Layer 1: 64 -> 64 -> 64, relu
    copy_kernel<<<cb, 256>>>((const float4*)x, (float4*)agg, n4);
    scatter_kernel<<<sb, 256>>>((const float4*)x, src, dst, ew, agg, E);
    mlp_kernel<64, true><<<mb, 256, sm64>>>((const float4*)agg, w11, b11, w12, b12, (float4*)h1, N);

    // Layer 2: 64 -> 128 -> 64, relu
    copy_kernel<<<cb, 256>>>((const float4*)h1, (float4*)agg, n4);
    scatter_kernel<<<sb, 256>>>((const float4*)h1, src, dst, ew, agg, E);
    mlp_kernel<128, true><<<mb, 256, sm128>>>((const float4*)agg, w21, b21, w22, b22, (float4*)h2, N);

    // Layer 3: 64 -> 64 -> 64, no relu
    copy_kernel<<<cb, 256>>>((const float4*)h2, (float4*)agg, n4);
    scatter_kernel<<<sb, 256>>>((const float4*)h2, src, dst, ew, agg, E);
    mlp_kernel<64, false><<<mb, 256, sm64>>>((const float4*)agg, w31, b31, w32, b32, (float4*)out, N);
}